// round 3
// baseline (speedup 1.0000x reference)
#include <cuda_runtime.h>
#include <cmath>
#include <complex>

// ============================================================================
// Selfmix: SO(3) self tensor product, LMAX=2, B x 1152 -> B x 3200 (fp32).
//
// Layout (m-major, channel-minor, 128 channels per l):
//   in : l=0 @ [0,128), l=1 @ [128,512) (3x128), l=2 @ [512,1152) (5x128)
//   out: lo=0 @ 0, lo=1 @ 128, lo=2 @ 512, lo=3 @ 1152, lo=4 @ 2048
//
// Per (b,c): out_lo[k] += sum_{ij} x_l1[i] x_l2[j] cg[i,j,k] * 0.5*mix[idx*128+c]
// plus keep path out_l[m] += x_l[m]*keep[l*128+c].
//
// Self-TP algebra: antisymmetric couplings (idx 5,8,17) vanish; mirror pairs
// merge with scale 0.5*(m_a + sigma*m_b), sigma=(-1)^(l1+l2-lo).
// ============================================================================

// ---------------- compile-time structural nonzero mask ----------------------
// Real-basis CG entry (a,b,c) can be nonzero only if:
//  (1) |mc| == |ma|+|mb|  or  |mc| == ||ma|-|mb||   (complex m3=m1+m2 rule)
//  (2) #(negative-m indices) has the same parity as l1+l2+lo (sin/cos parity)
__host__ __device__ constexpr bool structural(int l1, int l2, int lo,
                                              int a, int b, int c) {
  const int ma = a - l1, mb = b - l2, mc = c - lo;
  const int x = ma < 0 ? -ma : ma;
  const int y = mb < 0 ? -mb : mb;
  const int z = mc < 0 ? -mc : mc;
  const bool abs_ok = (z == x + y) || (z == (x > y ? x - y : y - x));
  const int nsin = (ma < 0 ? 1 : 0) + (mb < 0 ? 1 : 0) + (mc < 0 ? 1 : 0);
  const bool par_ok = ((nsin & 1) == ((l1 + l2 + lo) & 1));
  return abs_ok && par_ok;
}

// ---------------- by-value parameter block (constant bank) ------------------
struct Params {
  float c000[1][1][1];
  float c110[3][3][1];
  float c220[5][5][1];
  float c011[1][3][3];
  float c121[3][5][3];
  float c022[1][5][5];
  float c112[3][3][5];
  float c122[3][5][5];
  float c222[5][5][5];
  float c123[3][5][7];
  float c224[5][5][9];
};  // 689 floats = 2756 bytes

// ---------------- per-combo contraction, fully unrolled ---------------------
template <int L1, int L2, int LO>
__device__ __forceinline__ void combo(
    const float (&cg)[2 * L1 + 1][2 * L2 + 1][2 * LO + 1],
    const float (&xa)[2 * L1 + 1][2],
    const float (&xb)[2 * L2 + 1][2],
    float (&out)[2 * LO + 1][2],
    float s0, float s1) {
  // fold the per-channel scale into the smaller operand
  float ya[2 * L1 + 1][2];
#pragma unroll
  for (int a = 0; a < 2 * L1 + 1; a++) {
    ya[a][0] = xa[a][0] * s0;
    ya[a][1] = xa[a][1] * s1;
  }
#pragma unroll
  for (int a = 0; a < 2 * L1 + 1; a++) {
#pragma unroll
    for (int b = 0; b < 2 * L2 + 1; b++) {
      bool any = false;
#pragma unroll
      for (int c = 0; c < 2 * LO + 1; c++) any = any || structural(L1, L2, LO, a, b, c);
      if (any) {  // compile-time constant after unroll
        const float p0 = ya[a][0] * xb[b][0];
        const float p1 = ya[a][1] * xb[b][1];
#pragma unroll
        for (int c = 0; c < 2 * LO + 1; c++) {
          if (structural(L1, L2, LO, a, b, c)) {
            const float w = cg[a][b][c];
            out[c][0] = fmaf(w, p0, out[c][0]);
            out[c][1] = fmaf(w, p1, out[c][1]);
          }
        }
      }
    }
  }
}

// ---------------- kernel: one thread = one (b, channel-pair) ----------------
__global__ __launch_bounds__(128) void selfmix_kernel(
    const float* __restrict__ x, const float* __restrict__ keep,
    const float* __restrict__ mix, float* __restrict__ out,
    int nthreads, const __grid_constant__ Params p) {
  const int t = blockIdx.x * 128 + threadIdx.x;
  if (t >= nthreads) return;
  const int b = t >> 6;       // batch row
  const int cp = t & 63;      // channel pair index (channels 2cp, 2cp+1)

  // ---- load inputs (float2, fully coalesced) ----
  const float2* xr = reinterpret_cast<const float2*>(x) + (size_t)b * 576;
  float X0[1][2], X1[3][2], X2[5][2];
  {
    float2 v = xr[cp];
    X0[0][0] = v.x; X0[0][1] = v.y;
  }
#pragma unroll
  for (int m = 0; m < 3; m++) {
    float2 v = xr[64 + m * 64 + cp];
    X1[m][0] = v.x; X1[m][1] = v.y;
  }
#pragma unroll
  for (int m = 0; m < 5; m++) {
    float2 v = xr[256 + m * 64 + cp];
    X2[m][0] = v.x; X2[m][1] = v.y;
  }

  // ---- per-channel scale vectors (L1/L2-resident after first wave) ----
  const float2* kc = reinterpret_cast<const float2*>(keep);
  const float2 k0 = kc[cp], k1 = kc[64 + cp], k2 = kc[128 + cp];
  const float2* mv = reinterpret_cast<const float2*>(mix);
  const float2 m0  = mv[0 * 64 + cp],  m1  = mv[1 * 64 + cp];
  const float2 m2  = mv[2 * 64 + cp],  m3  = mv[3 * 64 + cp];
  const float2 m4  = mv[4 * 64 + cp],  m6  = mv[6 * 64 + cp];
  const float2 m7  = mv[7 * 64 + cp],  m9  = mv[9 * 64 + cp];
  const float2 m10 = mv[10 * 64 + cp], m11 = mv[11 * 64 + cp];
  const float2 m12 = mv[12 * 64 + cp], m13 = mv[13 * 64 + cp];
  const float2 m14 = mv[14 * 64 + cp], m15 = mv[15 * 64 + cp];
  const float2 m16 = mv[16 * 64 + cp], m18 = mv[18 * 64 + cp];

  float2* orow = reinterpret_cast<float2*>(out) + (size_t)b * 1600;

  // ---- lo = 4 : (2,2->4) ----
  {
    float O[9][2] = {};
    combo<2, 2, 4>(p.c224, X2, X2, O, 0.5f * m18.x, 0.5f * m18.y);
#pragma unroll
    for (int k = 0; k < 9; k++) {
      float2 w; w.x = O[k][0]; w.y = O[k][1];
      orow[1024 + k * 64 + cp] = w;
    }
  }
  // ---- lo = 3 : (1,2->3)+(2,1->3) merged (sigma=+1) ----
  {
    float O[7][2] = {};
    combo<1, 2, 3>(p.c123, X1, X2, O, 0.5f * (m15.x + m16.x), 0.5f * (m15.y + m16.y));
#pragma unroll
    for (int k = 0; k < 7; k++) {
      float2 w; w.x = O[k][0]; w.y = O[k][1];
      orow[576 + k * 64 + cp] = w;
    }
  }
  // ---- lo = 2 : (0,2)+(2,0), (1,1), (1,2)-(2,1) [sigma=-1], (2,2) + keep ----
  {
    float O[5][2] = {};
    combo<0, 2, 2>(p.c022, X0, X2, O, 0.5f * (m9.x + m12.x), 0.5f * (m9.y + m12.y));
    combo<1, 1, 2>(p.c112, X1, X1, O, 0.5f * m10.x, 0.5f * m10.y);
    combo<1, 2, 2>(p.c122, X1, X2, O, 0.5f * (m11.x - m13.x), 0.5f * (m11.y - m13.y));
    combo<2, 2, 2>(p.c222, X2, X2, O, 0.5f * m14.x, 0.5f * m14.y);
#pragma unroll
    for (int k = 0; k < 5; k++) {
      O[k][0] = fmaf(X2[k][0], k2.x, O[k][0]);
      O[k][1] = fmaf(X2[k][1], k2.y, O[k][1]);
      float2 w; w.x = O[k][0]; w.y = O[k][1];
      orow[256 + k * 64 + cp] = w;
    }
  }
  // ---- lo = 1 : (0,1)+(1,0), (1,2)+(2,1) [sigma=+1] + keep ----
  {
    float O[3][2] = {};
    combo<0, 1, 1>(p.c011, X0, X1, O, 0.5f * (m3.x + m4.x), 0.5f * (m3.y + m4.y));
    combo<1, 2, 1>(p.c121, X1, X2, O, 0.5f * (m6.x + m7.x), 0.5f * (m6.y + m7.y));
#pragma unroll
    for (int k = 0; k < 3; k++) {
      O[k][0] = fmaf(X1[k][0], k1.x, O[k][0]);
      O[k][1] = fmaf(X1[k][1], k1.y, O[k][1]);
      float2 w; w.x = O[k][0]; w.y = O[k][1];
      orow[64 + k * 64 + cp] = w;
    }
  }
  // ---- lo = 0 : (0,0), (1,1), (2,2) + keep ----
  {
    float O[1][2] = {};
    combo<0, 0, 0>(p.c000, X0, X0, O, 0.5f * m0.x, 0.5f * m0.y);
    combo<1, 1, 0>(p.c110, X1, X1, O, 0.5f * m1.x, 0.5f * m1.y);
    combo<2, 2, 0>(p.c220, X2, X2, O, 0.5f * m2.x, 0.5f * m2.y);
    O[0][0] = fmaf(X0[0][0], k0.x, O[0][0]);
    O[0][1] = fmaf(X0[0][1], k0.y, O[0][1]);
    float2 w; w.x = O[0][0]; w.y = O[0][1];
    orow[cp] = w;
  }
}

// ============================================================================
// Host: exact port of the reference CG construction (Racah + real basis).
// ============================================================================
static double factd(int n) {
  double r = 1.0;
  for (int i = 2; i <= n; i++) r *= (double)i;
  return r;
}

static void cg_complex_h(int l1, int l2, int l3, double C[5][5][9]) {
  for (int i = 0; i < 5; i++)
    for (int j = 0; j < 5; j++)
      for (int k = 0; k < 9; k++) C[i][j][k] = 0.0;
  for (int m1 = -l1; m1 <= l1; m1++) {
    for (int m2 = -l2; m2 <= l2; m2++) {
      const int m3 = m1 + m2;
      if (m3 < -l3 || m3 > l3) continue;
      double pre = std::sqrt((2 * l3 + 1) * factd(l1 + l2 - l3) * factd(l1 - l2 + l3) *
                             factd(-l1 + l2 + l3) / factd(l1 + l2 + l3 + 1));
      pre *= std::sqrt(factd(l3 + m3) * factd(l3 - m3) * factd(l1 - m1) *
                       factd(l1 + m1) * factd(l2 - m2) * factd(l2 + m2));
      double s = 0.0;
      for (int k = 0; k <= l1 + l2 - l3; k++) {
        const int den[6] = {k, l1 + l2 - l3 - k, l1 - m1 - k, l2 + m2 - k,
                            l3 - l2 + m1 + k, l3 - l1 - m2 + k};
        int mn = den[0];
        for (int t = 1; t < 6; t++) mn = den[t] < mn ? den[t] : mn;
        if (mn < 0) continue;
        double d = 1.0;
        for (int t = 0; t < 6; t++) d *= factd(den[t]);
        s += ((k & 1) ? -1.0 : 1.0) / d;
      }
      C[m1 + l1][m2 + l2][m3 + l3] = pre * s;
    }
  }
}

static void build_u(int l, std::complex<double> U[9][9]) {
  for (int i = 0; i < 9; i++)
    for (int j = 0; j < 9; j++) U[i][j] = 0.0;
  U[l][l] = 1.0;
  const double is2 = 1.0 / std::sqrt(2.0);
  for (int m = 1; m <= l; m++) {
    const double sgn = (m & 1) ? -1.0 : 1.0;
    U[l + m][l + m] = sgn * is2;
    U[l + m][l - m] = is2;
    U[l - m][l - m] = std::complex<double>(0.0, is2);
    U[l - m][l + m] = std::complex<double>(0.0, -sgn * is2);
  }
}

static void cg_real_h(int l1, int l2, int l3, float* R) {
  const int d1 = 2 * l1 + 1, d2 = 2 * l2 + 1, d3 = 2 * l3 + 1;
  double C[5][5][9];
  cg_complex_h(l1, l2, l3, C);
  std::complex<double> U1[9][9], U2[9][9], U3[9][9];
  build_u(l1, U1);
  build_u(l2, U2);
  build_u(l3, U3);
  double Rre[5][5][9], Rim[5][5][9];
  double mxre = 0.0, mxim = 0.0;
  for (int a = 0; a < d1; a++) {
    for (int b = 0; b < d2; b++) {
      for (int c = 0; c < d3; c++) {
        std::complex<double> acc(0.0, 0.0);
        for (int i = 0; i < d1; i++)
          for (int j = 0; j < d2; j++)
            for (int k = 0; k < d3; k++) {
              if (C[i][j][k] == 0.0) continue;
              acc += U1[a][i] * U2[b][j] * std::conj(U3[c][k]) * C[i][j][k];
            }
        Rre[a][b][c] = acc.real();
        Rim[a][b][c] = acc.imag();
        if (std::fabs(acc.real()) > mxre) mxre = std::fabs(acc.real());
        if (std::fabs(acc.imag()) > mxim) mxim = std::fabs(acc.imag());
      }
    }
  }
  const bool use_im = mxim > mxre;
  for (int a = 0; a < d1; a++)
    for (int b = 0; b < d2; b++)
      for (int c = 0; c < d3; c++)
        R[(a * d2 + b) * d3 + c] = (float)(use_im ? Rim[a][b][c] : Rre[a][b][c]);
}

static void build_params(Params& p) {
  cg_real_h(0, 0, 0, &p.c000[0][0][0]);
  cg_real_h(1, 1, 0, &p.c110[0][0][0]);
  cg_real_h(2, 2, 0, &p.c220[0][0][0]);
  cg_real_h(0, 1, 1, &p.c011[0][0][0]);
  cg_real_h(1, 2, 1, &p.c121[0][0][0]);
  cg_real_h(0, 2, 2, &p.c022[0][0][0]);
  cg_real_h(1, 1, 2, &p.c112[0][0][0]);
  cg_real_h(1, 2, 2, &p.c122[0][0][0]);
  cg_real_h(2, 2, 2, &p.c222[0][0][0]);
  cg_real_h(1, 2, 3, &p.c123[0][0][0]);
  cg_real_h(2, 2, 4, &p.c224[0][0][0]);
}

// ============================================================================
extern "C" void kernel_launch(void* const* d_in, const int* in_sizes, int n_in,
                              void* d_out, int out_size) {
  (void)n_in;
  (void)out_size;
  const float* x = (const float*)d_in[0];       // (B, 1152)
  const float* keep = (const float*)d_in[1];    // (384,)
  const float* mix = (const float*)d_in[2];     // (2432,)
  float* out = (float*)d_out;                   // (B, 3200)

  const int B = in_sizes[0] / 1152;
  Params p;
  build_params(p);

  const int nthreads = B * 64;                  // 2 channels per thread
  const int block = 128;
  const int grid = (nthreads + block - 1) / block;
  selfmix_kernel<<<grid, block>>>(x, keep, mix, out, nthreads, p);
}

// round 5
// speedup vs baseline: 1.0061x; 1.0061x over previous
#include <cuda_runtime.h>
#include <cmath>
#include <complex>

// ============================================================================
// Selfmix: SO(3) self tensor product, LMAX=2, B x 1152 -> B x 3200 (fp32).
// R4 = R3 resubmitted (infra failure last round): 4 channels per thread
// (float4), evict-first stores (__stcs) so the 75.5MB input stays L2-resident
// across graph replays (L2 = 126MB).
// ============================================================================

// ---------------- compile-time structural nonzero mask ----------------------
__host__ __device__ constexpr bool structural(int l1, int l2, int lo,
                                              int a, int b, int c) {
  const int ma = a - l1, mb = b - l2, mc = c - lo;
  const int x = ma < 0 ? -ma : ma;
  const int y = mb < 0 ? -mb : mb;
  const int z = mc < 0 ? -mc : mc;
  const bool abs_ok = (z == x + y) || (z == (x > y ? x - y : y - x));
  const int nsin = (ma < 0 ? 1 : 0) + (mb < 0 ? 1 : 0) + (mc < 0 ? 1 : 0);
  const bool par_ok = ((nsin & 1) == ((l1 + l2 + lo) & 1));
  return abs_ok && par_ok;
}

// ---------------- by-value parameter block (constant bank) ------------------
struct Params {
  float c000[1][1][1];
  float c110[3][3][1];
  float c220[5][5][1];
  float c011[1][3][3];
  float c121[3][5][3];
  float c022[1][5][5];
  float c112[3][3][5];
  float c122[3][5][5];
  float c222[5][5][5];
  float c123[3][5][7];
  float c224[5][5][9];
};  // 689 floats = 2756 bytes

// ---------------- per-combo contraction, fully unrolled, 4 lanes ------------
template <int L1, int L2, int LO>
__device__ __forceinline__ void combo(
    const float (&cg)[2 * L1 + 1][2 * L2 + 1][2 * LO + 1],
    const float (&xa)[2 * L1 + 1][4],
    const float (&xb)[2 * L2 + 1][4],
    float (&out)[2 * LO + 1][4],
    const float (&s)[4]) {
  float ya[2 * L1 + 1][4];
#pragma unroll
  for (int a = 0; a < 2 * L1 + 1; a++)
#pragma unroll
    for (int v = 0; v < 4; v++) ya[a][v] = xa[a][v] * s[v];
#pragma unroll
  for (int a = 0; a < 2 * L1 + 1; a++) {
#pragma unroll
    for (int b = 0; b < 2 * L2 + 1; b++) {
      bool any = false;
#pragma unroll
      for (int c = 0; c < 2 * LO + 1; c++) any = any || structural(L1, L2, LO, a, b, c);
      if (any) {  // compile-time constant after unroll
        float p[4];
#pragma unroll
        for (int v = 0; v < 4; v++) p[v] = ya[a][v] * xb[b][v];
#pragma unroll
        for (int c = 0; c < 2 * LO + 1; c++) {
          if (structural(L1, L2, LO, a, b, c)) {
            const float w = cg[a][b][c];
#pragma unroll
            for (int v = 0; v < 4; v++) out[c][v] = fmaf(w, p[v], out[c][v]);
          }
        }
      }
    }
  }
}

__device__ __forceinline__ void scale_comb(float (&d)[4], float4 a, float4 b, float sgn) {
  d[0] = 0.5f * fmaf(sgn, b.x, a.x);
  d[1] = 0.5f * fmaf(sgn, b.y, a.y);
  d[2] = 0.5f * fmaf(sgn, b.z, a.z);
  d[3] = 0.5f * fmaf(sgn, b.w, a.w);
}
__device__ __forceinline__ void scale_one(float (&d)[4], float4 a) {
  d[0] = 0.5f * a.x; d[1] = 0.5f * a.y; d[2] = 0.5f * a.z; d[3] = 0.5f * a.w;
}

// ---------------- kernel: one thread = one (b, channel-quad) ----------------
__global__ __launch_bounds__(128) void selfmix_kernel(
    const float* __restrict__ x, const float* __restrict__ keep,
    const float* __restrict__ mix, float* __restrict__ out,
    int nthreads, const __grid_constant__ Params p) {
  const int t = blockIdx.x * 128 + threadIdx.x;
  if (t >= nthreads) return;
  const int b = t >> 5;       // batch row (warp == one row)
  const int cq = t & 31;      // channel quad (channels 4cq..4cq+3)

  // ---- load inputs (float4, 512B contiguous per warp-row) ----
  const float4* xr = reinterpret_cast<const float4*>(x) + (size_t)b * 288;
  float X0[1][4], X1[3][4], X2[5][4];
  {
    float4 v = xr[cq];
    X0[0][0] = v.x; X0[0][1] = v.y; X0[0][2] = v.z; X0[0][3] = v.w;
  }
#pragma unroll
  for (int m = 0; m < 3; m++) {
    float4 v = xr[32 + m * 32 + cq];
    X1[m][0] = v.x; X1[m][1] = v.y; X1[m][2] = v.z; X1[m][3] = v.w;
  }
#pragma unroll
  for (int m = 0; m < 5; m++) {
    float4 v = xr[128 + m * 32 + cq];
    X2[m][0] = v.x; X2[m][1] = v.y; X2[m][2] = v.z; X2[m][3] = v.w;
  }

  // ---- per-channel scales, merged per combo (L2-resident, tiny) ----
  const float4* kc = reinterpret_cast<const float4*>(keep);
  const float4 k0 = kc[cq], k1 = kc[32 + cq], k2 = kc[64 + cq];
  const float4* mv = reinterpret_cast<const float4*>(mix);
  float s000[4], s110[4], s220[4], s011[4], s121[4];
  float s022[4], s112[4], s122[4], s222[4], s123[4], s224[4];
  scale_one (s000, mv[0 * 32 + cq]);
  scale_one (s110, mv[1 * 32 + cq]);
  scale_one (s220, mv[2 * 32 + cq]);
  scale_comb(s011, mv[3 * 32 + cq],  mv[4 * 32 + cq],  1.f);   // (0,1)+(1,0)
  scale_comb(s121, mv[6 * 32 + cq],  mv[7 * 32 + cq],  1.f);   // (1,2)+(2,1)->1
  scale_comb(s022, mv[9 * 32 + cq],  mv[12 * 32 + cq], 1.f);   // (0,2)+(2,0)
  scale_one (s112, mv[10 * 32 + cq]);
  scale_comb(s122, mv[11 * 32 + cq], mv[13 * 32 + cq], -1.f);  // (1,2)-(2,1)->2
  scale_one (s222, mv[14 * 32 + cq]);
  scale_comb(s123, mv[15 * 32 + cq], mv[16 * 32 + cq], 1.f);   // (1,2)+(2,1)->3
  scale_one (s224, mv[18 * 32 + cq]);

  float4* orow = reinterpret_cast<float4*>(out) + (size_t)b * 800;

  // ---- lo = 4 : (2,2->4) ----
  {
    float O[9][4] = {};
    combo<2, 2, 4>(p.c224, X2, X2, O, s224);
#pragma unroll
    for (int k = 0; k < 9; k++)
      __stcs(&orow[512 + k * 32 + cq], make_float4(O[k][0], O[k][1], O[k][2], O[k][3]));
  }
  // ---- lo = 3 : (1,2->3)+(2,1->3) merged ----
  {
    float O[7][4] = {};
    combo<1, 2, 3>(p.c123, X1, X2, O, s123);
#pragma unroll
    for (int k = 0; k < 7; k++)
      __stcs(&orow[288 + k * 32 + cq], make_float4(O[k][0], O[k][1], O[k][2], O[k][3]));
  }
  // ---- lo = 2 ----
  {
    float O[5][4] = {};
    combo<0, 2, 2>(p.c022, X0, X2, O, s022);
    combo<1, 1, 2>(p.c112, X1, X1, O, s112);
    combo<1, 2, 2>(p.c122, X1, X2, O, s122);
    combo<2, 2, 2>(p.c222, X2, X2, O, s222);
    const float kk[4] = {k2.x, k2.y, k2.z, k2.w};
#pragma unroll
    for (int k = 0; k < 5; k++) {
#pragma unroll
      for (int v = 0; v < 4; v++) O[k][v] = fmaf(X2[k][v], kk[v], O[k][v]);
      __stcs(&orow[128 + k * 32 + cq], make_float4(O[k][0], O[k][1], O[k][2], O[k][3]));
    }
  }
  // ---- lo = 1 ----
  {
    float O[3][4] = {};
    combo<0, 1, 1>(p.c011, X0, X1, O, s011);
    combo<1, 2, 1>(p.c121, X1, X2, O, s121);
    const float kk[4] = {k1.x, k1.y, k1.z, k1.w};
#pragma unroll
    for (int k = 0; k < 3; k++) {
#pragma unroll
      for (int v = 0; v < 4; v++) O[k][v] = fmaf(X1[k][v], kk[v], O[k][v]);
      __stcs(&orow[32 + k * 32 + cq], make_float4(O[k][0], O[k][1], O[k][2], O[k][3]));
    }
  }
  // ---- lo = 0 ----
  {
    float O[1][4] = {};
    combo<0, 0, 0>(p.c000, X0, X0, O, s000);
    combo<1, 1, 0>(p.c110, X1, X1, O, s110);
    combo<2, 2, 0>(p.c220, X2, X2, O, s220);
    const float kk[4] = {k0.x, k0.y, k0.z, k0.w};
#pragma unroll
    for (int v = 0; v < 4; v++) O[0][v] = fmaf(X0[0][v], kk[v], O[0][v]);
    __stcs(&orow[cq], make_float4(O[0][0], O[0][1], O[0][2], O[0][3]));
  }
}

// ============================================================================
// Host: exact port of the reference CG construction (Racah + real basis).
// ============================================================================
static double factd(int n) {
  double r = 1.0;
  for (int i = 2; i <= n; i++) r *= (double)i;
  return r;
}

static void cg_complex_h(int l1, int l2, int l3, double C[5][5][9]) {
  for (int i = 0; i < 5; i++)
    for (int j = 0; j < 5; j++)
      for (int k = 0; k < 9; k++) C[i][j][k] = 0.0;
  for (int m1 = -l1; m1 <= l1; m1++) {
    for (int m2 = -l2; m2 <= l2; m2++) {
      const int m3 = m1 + m2;
      if (m3 < -l3 || m3 > l3) continue;
      double pre = std::sqrt((2 * l3 + 1) * factd(l1 + l2 - l3) * factd(l1 - l2 + l3) *
                             factd(-l1 + l2 + l3) / factd(l1 + l2 + l3 + 1));
      pre *= std::sqrt(factd(l3 + m3) * factd(l3 - m3) * factd(l1 - m1) *
                       factd(l1 + m1) * factd(l2 - m2) * factd(l2 + m2));
      double s = 0.0;
      for (int k = 0; k <= l1 + l2 - l3; k++) {
        const int den[6] = {k, l1 + l2 - l3 - k, l1 - m1 - k, l2 + m2 - k,
                            l3 - l2 + m1 + k, l3 - l1 - m2 + k};
        int mn = den[0];
        for (int t = 1; t < 6; t++) mn = den[t] < mn ? den[t] : mn;
        if (mn < 0) continue;
        double d = 1.0;
        for (int t = 0; t < 6; t++) d *= factd(den[t]);
        s += ((k & 1) ? -1.0 : 1.0) / d;
      }
      C[m1 + l1][m2 + l2][m3 + l3] = pre * s;
    }
  }
}

static void build_u(int l, std::complex<double> U[9][9]) {
  for (int i = 0; i < 9; i++)
    for (int j = 0; j < 9; j++) U[i][j] = 0.0;
  U[l][l] = 1.0;
  const double is2 = 1.0 / std::sqrt(2.0);
  for (int m = 1; m <= l; m++) {
    const double sgn = (m & 1) ? -1.0 : 1.0;
    U[l + m][l + m] = sgn * is2;
    U[l + m][l - m] = is2;
    U[l - m][l - m] = std::complex<double>(0.0, is2);
    U[l - m][l + m] = std::complex<double>(0.0, -sgn * is2);
  }
}

static void cg_real_h(int l1, int l2, int l3, float* R) {
  const int d1 = 2 * l1 + 1, d2 = 2 * l2 + 1, d3 = 2 * l3 + 1;
  double C[5][5][9];
  cg_complex_h(l1, l2, l3, C);
  std::complex<double> U1[9][9], U2[9][9], U3[9][9];
  build_u(l1, U1);
  build_u(l2, U2);
  build_u(l3, U3);
  double Rre[5][5][9], Rim[5][5][9];
  double mxre = 0.0, mxim = 0.0;
  for (int a = 0; a < d1; a++) {
    for (int b = 0; b < d2; b++) {
      for (int c = 0; c < d3; c++) {
        std::complex<double> acc(0.0, 0.0);
        for (int i = 0; i < d1; i++)
          for (int j = 0; j < d2; j++)
            for (int k = 0; k < d3; k++) {
              if (C[i][j][k] == 0.0) continue;
              acc += U1[a][i] * U2[b][j] * std::conj(U3[c][k]) * C[i][j][k];
            }
        Rre[a][b][c] = acc.real();
        Rim[a][b][c] = acc.imag();
        if (std::fabs(acc.real()) > mxre) mxre = std::fabs(acc.real());
        if (std::fabs(acc.imag()) > mxim) mxim = std::fabs(acc.imag());
      }
    }
  }
  const bool use_im = mxim > mxre;
  for (int a = 0; a < d1; a++)
    for (int b = 0; b < d2; b++)
      for (int c = 0; c < d3; c++)
        R[(a * d2 + b) * d3 + c] = (float)(use_im ? Rim[a][b][c] : Rre[a][b][c]);
}

static void build_params(Params& p) {
  cg_real_h(0, 0, 0, &p.c000[0][0][0]);
  cg_real_h(1, 1, 0, &p.c110[0][0][0]);
  cg_real_h(2, 2, 0, &p.c220[0][0][0]);
  cg_real_h(0, 1, 1, &p.c011[0][0][0]);
  cg_real_h(1, 2, 1, &p.c121[0][0][0]);
  cg_real_h(0, 2, 2, &p.c022[0][0][0]);
  cg_real_h(1, 1, 2, &p.c112[0][0][0]);
  cg_real_h(1, 2, 2, &p.c122[0][0][0]);
  cg_real_h(2, 2, 2, &p.c222[0][0][0]);
  cg_real_h(1, 2, 3, &p.c123[0][0][0]);
  cg_real_h(2, 2, 4, &p.c224[0][0][0]);
}

// ============================================================================
extern "C" void kernel_launch(void* const* d_in, const int* in_sizes, int n_in,
                              void* d_out, int out_size) {
  (void)n_in;
  (void)out_size;
  const float* x = (const float*)d_in[0];       // (B, 1152)
  const float* keep = (const float*)d_in[1];    // (384,)
  const float* mix = (const float*)d_in[2];     // (2432,)
  float* out = (float*)d_out;                   // (B, 3200)

  const int B = in_sizes[0] / 1152;
  Params p;
  build_params(p);

  const int nthreads = B * 32;                  // 4 channels per thread
  const int block = 128;
  const int grid = (nthreads + block - 1) / block;
  selfmix_kernel<<<grid, block>>>(x, keep, mix, out, nthreads, p);
}